// round 9
// baseline (speedup 1.0000x reference)
#include <cuda_runtime.h>
#include <cuda_bf16.h>
#include <cstdint>

// out[b,t,s] = dot(q[b,t,:], E_h[s - t/4 + 255]),  h = b % 8
//   E_h[j] = e1[h*256 + j]        j in [0,256)
//   E_h[j] = e2[h*256 + j - 255]  j in [256,511)
// B=128, T=1024, S=256, D=64.
//
// Per block: one b, 128 t-rows, 128 s-cols. Banded GEMM M=128 x N=160 x K=192
// (truncation bf16 split: D = qh*Eh + qh*El + ql*Eh; ql*El ~2^-16 dropped).
// out[t][s] = D[t][ s + 31 - t/4 ]  -> direct predicated STG epilogue (no smem stage).
// Tiles: XOR-swizzled 128B rows, conflict-free LDSM, no padding.

#define T_DIM 1024
#define S_DIM 256
#define D_DIM 64

constexpr int BT = 128;
constexpr int NW = 160;

constexpr int SM_AH = 0;
constexpr int SM_AL = SM_AH + BT * 128;      // 16384
constexpr int SM_BH = SM_AL + BT * 128;      // 32768
constexpr int SM_BL = SM_BH + NW * 128;      // 53248
constexpr int SM_TOTAL = SM_BL + NW * 128;   // 73728

__device__ __forceinline__ uint32_t smem_u32(const void* p) {
    uint32_t a;
    asm("{ .reg .u64 t; cvta.to.shared.u64 t, %1; cvt.u32.u64 %0, t; }"
        : "=r"(a) : "l"(p));
    return a;
}

#define LDSM_X4(r0, r1, r2, r3, addr)                                        \
    asm volatile("ldmatrix.sync.aligned.m8n8.x4.shared.b16 {%0,%1,%2,%3}, [%4];" \
                 : "=r"(r0), "=r"(r1), "=r"(r2), "=r"(r3) : "r"(addr))

#define LDSM_X2(r0, r1, addr)                                                \
    asm volatile("ldmatrix.sync.aligned.m8n8.x2.shared.b16 {%0,%1}, [%2];"   \
                 : "=r"(r0), "=r"(r1) : "r"(addr))

#define MMA16816(d, a, bb)                                                   \
    asm volatile("mma.sync.aligned.m16n8k16.row.col.f32.bf16.bf16.f32 "      \
                 "{%0,%1,%2,%3}, {%4,%5,%6,%7}, {%8,%9}, {%0,%1,%2,%3};"     \
                 : "+f"((d)[0]), "+f"((d)[1]), "+f"((d)[2]), "+f"((d)[3])    \
                 : "r"((a)[0]), "r"((a)[1]), "r"((a)[2]), "r"((a)[3]),       \
                   "r"((bb)[0]), "r"((bb)[1]))

// truncation split: hi = top16 bits (packed pair), lo = exact bf16 remainder
__device__ __forceinline__ void split2t(float a, float b, uint32_t& hi, uint32_t& lo) {
    uint32_t ua = __float_as_uint(a), ub = __float_as_uint(b);
    hi = __byte_perm(ua, ub, 0x7632);
    float ra = a - __uint_as_float(ua & 0xFFFF0000u);
    float rb = b - __uint_as_float(ub & 0xFFFF0000u);
    __nv_bfloat162 L = __floats2bfloat162_rn(ra, rb);
    lo = *reinterpret_cast<uint32_t*>(&L);
}

// swizzled byte offset of (row, 16B-chunk) in a 128B-row tile
__device__ __forceinline__ uint32_t swz(int row, int chunk) {
    return (uint32_t)(row * 128 + ((chunk ^ (row & 7)) << 4));
}

__global__ void __launch_bounds__(256, 2)
srel_mma(const float* __restrict__ q,
         const float* __restrict__ e1,
         const float* __restrict__ e2,
         float* __restrict__ out)
{
    extern __shared__ char smem[];
    const uint32_t sb = smem_u32(smem);
    const int tid  = threadIdx.x;
    const int lane = tid & 31;
    const int wid  = tid >> 5;

    const int b   = blockIdx.z;
    const int h   = b & 7;
    const int t0  = blockIdx.x * BT;
    const int sx  = blockIdx.y;
    const int sh0 = t0 >> 2;
    const int jmin = 128 * sx + 224 - sh0;   // window col c = j - jmin, c in [0,159]

    // ---- stage Q: batch LDG, split, swizzled STS ----
    {
        const float* qb = q + ((size_t)b * T_DIM + t0) * D_DIM;
        float4 v[8];
        #pragma unroll
        for (int i = 0; i < 8; i++) {
            int idx = tid + 256 * i;
            v[i] = *reinterpret_cast<const float4*>(qb + (idx >> 4) * D_DIM + 4 * (idx & 15));
        }
        #pragma unroll
        for (int i = 0; i < 8; i++) {
            int idx = tid + 256 * i;
            int row = idx >> 4, m = idx & 15;
            uint32_t h0, l0, h1, l1;
            split2t(v[i].x, v[i].y, h0, l0);
            split2t(v[i].z, v[i].w, h1, l1);
            uint32_t off = swz(row, m >> 1) + (m & 1) * 8;
            uint32_t* pH = reinterpret_cast<uint32_t*>(smem + SM_AH + off);
            uint32_t* pL = reinterpret_cast<uint32_t*>(smem + SM_AL + off);
            pH[0] = h0; pH[1] = h1;
            pL[0] = l0; pL[1] = l1;
        }
    }
    // ---- stage E window (160 rows) ----
    {
        float4 v[10];
        #pragma unroll
        for (int i = 0; i < 10; i++) {
            int idx = tid + 256 * i;
            int r = idx >> 4;
            int j = jmin + r;
            if (j > 510) j = 510;   // window col 159 never consumed
            const float* src = (j < 256)
                ? (e1 + (size_t)(h * 256 + j) * D_DIM)
                : (e2 + (size_t)(h * 256 + j - 255) * D_DIM);
            v[i] = *reinterpret_cast<const float4*>(src + 4 * (idx & 15));
        }
        #pragma unroll
        for (int i = 0; i < 10; i++) {
            int idx = tid + 256 * i;
            int r = idx >> 4, m = idx & 15;
            uint32_t h0, l0, h1, l1;
            split2t(v[i].x, v[i].y, h0, l0);
            split2t(v[i].z, v[i].w, h1, l1);
            uint32_t off = swz(r, m >> 1) + (m & 1) * 8;
            uint32_t* pH = reinterpret_cast<uint32_t*>(smem + SM_BH + off);
            uint32_t* pL = reinterpret_cast<uint32_t*>(smem + SM_BL + off);
            pH[0] = h0; pH[1] = h1;
            pL[0] = l0; pL[1] = l1;
        }
    }
    __syncthreads();

    // ---- warp tiling: 8 warps = 2 (M halves of 64) x 4 (N quarters of 40) ----
    const int wm = wid & 1;
    const int wn = wid >> 1;
    const int g  = lane >> 2;
    const int tg = lane & 3;

    float acc[4][5][4] = {};

    // A ldmatrix: rows wm*64 + (lane&15) + mt*16, chunk kk*2 + (lane>>4)
    const int arow = wm * 64 + (lane & 15);
    const int achk = lane >> 4;
    // B ldmatrix x4 pair: rows wn*40 + p*16 + (lane>>4)*8 + (lane&7), chunk kk*2 + ((lane>>3)&1)
    const int brow = wn * 40 + (lane >> 4) * 8 + (lane & 7);
    const int bchk = (lane >> 3) & 1;
    const int brow2 = wn * 40 + (lane & 7);   // x2 tail (tile 4)

    #pragma unroll
    for (int kk = 0; kk < 4; kk++) {
        uint32_t aH[4][4], aL[4][4], bH[5][2], bL[5][2];
        const uint32_t aoff  = swz(arow, kk * 2 + achk);
        const uint32_t boff  = swz(brow, kk * 2 + bchk);
        const uint32_t boff2 = swz(brow2, kk * 2 + bchk);

        // pass 1: qh * Eh
        #pragma unroll
        for (int mt = 0; mt < 4; mt++)
            LDSM_X4(aH[mt][0], aH[mt][1], aH[mt][2], aH[mt][3],
                    sb + SM_AH + aoff + mt * 2048);
        #pragma unroll
        for (int p = 0; p < 2; p++)
            LDSM_X4(bH[2*p][0], bH[2*p][1], bH[2*p+1][0], bH[2*p+1][1],
                    sb + SM_BH + boff + p * 2048);
        LDSM_X2(bH[4][0], bH[4][1], sb + SM_BH + boff2 + 4096);
        #pragma unroll
        for (int mt = 0; mt < 4; mt++)
            #pragma unroll
            for (int nt = 0; nt < 5; nt++)
                MMA16816(acc[mt][nt], aH[mt], bH[nt]);

        // pass 2: qh * El (reuse aH)
        #pragma unroll
        for (int p = 0; p < 2; p++)
            LDSM_X4(bL[2*p][0], bL[2*p][1], bL[2*p+1][0], bL[2*p+1][1],
                    sb + SM_BL + boff + p * 2048);
        LDSM_X2(bL[4][0], bL[4][1], sb + SM_BL + boff2 + 4096);
        #pragma unroll
        for (int mt = 0; mt < 4; mt++)
            #pragma unroll
            for (int nt = 0; nt < 5; nt++)
                MMA16816(acc[mt][nt], aH[mt], bL[nt]);

        // pass 3: ql * Eh (reuse bH)
        #pragma unroll
        for (int mt = 0; mt < 4; mt++)
            LDSM_X4(aL[mt][0], aL[mt][1], aL[mt][2], aL[mt][3],
                    sb + SM_AL + aoff + mt * 2048);
        #pragma unroll
        for (int mt = 0; mt < 4; mt++)
            #pragma unroll
            for (int nt = 0; nt < 5; nt++)
                MMA16816(acc[mt][nt], aL[mt], bH[nt]);
    }

    // ---- direct epilogue: shifted predicated stores, no smem stage ----
    // fragment element (row, window col n): out col = n - (31 - row/4)
    float* ob = out + ((size_t)b * T_DIM + t0) * S_DIM + 128 * sx;
    #pragma unroll
    for (int mt = 0; mt < 4; mt++) {
        const int r0 = wm * 64 + mt * 16 + g;     // rows r0 and r0+8
        const int off0 = 31 - (r0 >> 2);
        const int off1 = 31 - ((r0 + 8) >> 2);    // = off0 - 2
        float* p0 = ob + (size_t)r0 * S_DIM;
        float* p1 = p0 + 8 * S_DIM;
        #pragma unroll
        for (int nt = 0; nt < 5; nt++) {
            const int n = wn * 40 + nt * 8 + 2 * tg;
            int c0 = n - off0;
            int c1 = n - off1;
            if ((unsigned)c0       < 128u) p0[c0]     = acc[mt][nt][0];
            if ((unsigned)(c0 + 1) < 128u) p0[c0 + 1] = acc[mt][nt][1];
            if ((unsigned)c1       < 128u) p1[c1]     = acc[mt][nt][2];
            if ((unsigned)(c1 + 1) < 128u) p1[c1 + 1] = acc[mt][nt][3];
        }
    }
}

extern "C" void kernel_launch(void* const* d_in, const int* in_sizes, int n_in,
                              void* d_out, int out_size)
{
    const float* q  = (const float*)d_in[0];
    const float* e1 = (const float*)d_in[1];
    const float* e2 = (const float*)d_in[2];
    float* out = (float*)d_out;

    cudaFuncSetAttribute(srel_mma,
                         cudaFuncAttributeMaxDynamicSharedMemorySize, SM_TOTAL);
    dim3 grid(T_DIM / BT, S_DIM / 128, 128);   // (8, 2, 128) = 2048 blocks
    srel_mma<<<grid, 256, SM_TOTAL>>>(q, e1, e2, out);
}

// round 10
// speedup vs baseline: 1.0848x; 1.0848x over previous
#include <cuda_runtime.h>
#include <cuda_fp16.h>
#include <cstdint>

// out[b,t,s] = dot(q[b,t,:], E_h[s - t/4 + 255]),  h = b % 8
//   E_h[j] = e1[h*256 + j]        j in [0,256)
//   E_h[j] = e2[h*256 + j - 255]  j in [256,511)
// B=128, T=1024, S=256, D=64.
//
// Per block: one b, 128 t-rows, 128 s-cols. Banded GEMM M=128 x N=160 x K=128:
//   fp16 2-pass: D = q̂·Eh + q̂·El,  q̂ = fp16(q), Eh = fp16(E), El = fp16(E - Eh)
//   (error ~2^-12 rms, well under 1e-3)
// out[t][s] = D[t][ s + 31 - t/4 ], via conflict-free smem stage.

#define T_DIM 1024
#define S_DIM 256
#define D_DIM 64

constexpr int BT = 128;
constexpr int NW = 160;
constexpr int RSTRIDE = 144;     // bytes per fp16 row: conflict-free LDSM
constexpr int SP = 168;          // fp32 staging stride (floats)

constexpr int SM_A  = 0;
constexpr int SM_BH = SM_A  + BT * RSTRIDE;      // 18432
constexpr int SM_BL = SM_BH + NW * RSTRIDE;      // 41472
constexpr int SM_IN_END = SM_BL + NW * RSTRIDE;  // 64512
constexpr int SM_TOTAL = BT * SP * 4;            // 86016 (stage aliases inputs)
static_assert(SM_TOTAL >= SM_IN_END, "stage must cover inputs");

__device__ __forceinline__ uint32_t smem_u32(const void* p) {
    uint32_t a;
    asm("{ .reg .u64 t; cvta.to.shared.u64 t, %1; cvt.u32.u64 %0, t; }"
        : "=r"(a) : "l"(p));
    return a;
}

#define LDSM_X4(r0, r1, r2, r3, addr)                                        \
    asm volatile("ldmatrix.sync.aligned.m8n8.x4.shared.b16 {%0,%1,%2,%3}, [%4];" \
                 : "=r"(r0), "=r"(r1), "=r"(r2), "=r"(r3) : "r"(addr))

#define LDSM_X2(r0, r1, addr)                                                \
    asm volatile("ldmatrix.sync.aligned.m8n8.x2.shared.b16 {%0,%1}, [%2];"   \
                 : "=r"(r0), "=r"(r1) : "r"(addr))

#define MMA16816(d, a, bb)                                                   \
    asm volatile("mma.sync.aligned.m16n8k16.row.col.f32.f16.f16.f32 "        \
                 "{%0,%1,%2,%3}, {%4,%5,%6,%7}, {%8,%9}, {%0,%1,%2,%3};"     \
                 : "+f"((d)[0]), "+f"((d)[1]), "+f"((d)[2]), "+f"((d)[3])    \
                 : "r"((a)[0]), "r"((a)[1]), "r"((a)[2]), "r"((a)[3]),       \
                   "r"((bb)[0]), "r"((bb)[1]))

// fp16 split of two floats: hi = rn(fp16), lo = rn(fp16(residual))
__device__ __forceinline__ void split2h(float a, float b, uint32_t& hi, uint32_t& lo) {
    __half2 H = __floats2half2_rn(a, b);
    float ra = a - __half2float(__low2half(H));
    float rb = b - __half2float(__high2half(H));
    __half2 L = __floats2half2_rn(ra, rb);
    hi = *reinterpret_cast<uint32_t*>(&H);
    lo = *reinterpret_cast<uint32_t*>(&L);
}

__global__ void __launch_bounds__(256, 2)
srel_mma(const float* __restrict__ q,
         const float* __restrict__ e1,
         const float* __restrict__ e2,
         float* __restrict__ out)
{
    extern __shared__ char smem[];
    const uint32_t sb = smem_u32(smem);
    const int tid  = threadIdx.x;
    const int lane = tid & 31;
    const int wid  = tid >> 5;

    const int b   = blockIdx.z;
    const int h   = b & 7;
    const int t0  = blockIdx.x * BT;
    const int sx  = blockIdx.y;
    const int sh0 = t0 >> 2;
    const int jmin = 128 * sx + 224 - sh0;   // window col c = j - jmin, c in [0,159]

    // ---- stage Q as single fp16 tile (batch LDG for MLP) ----
    {
        const float* qb = q + ((size_t)b * T_DIM + t0) * D_DIM;
        float4 v[8];
        #pragma unroll
        for (int i = 0; i < 8; i++) {
            int idx = tid + 256 * i;
            v[i] = *reinterpret_cast<const float4*>(qb + (idx >> 4) * D_DIM + 4 * (idx & 15));
        }
        #pragma unroll
        for (int i = 0; i < 8; i++) {
            int idx = tid + 256 * i;
            int row = idx >> 4, m = idx & 15;
            __half2 h0 = __floats2half2_rn(v[i].x, v[i].y);
            __half2 h1 = __floats2half2_rn(v[i].z, v[i].w);
            uint32_t* pA = reinterpret_cast<uint32_t*>(smem + SM_A + row * RSTRIDE + 8 * m);
            pA[0] = *reinterpret_cast<uint32_t*>(&h0);
            pA[1] = *reinterpret_cast<uint32_t*>(&h1);
        }
    }
    // ---- stage E window: fp16 hi/lo tiles ----
    {
        float4 v[10];
        #pragma unroll
        for (int i = 0; i < 10; i++) {
            int idx = tid + 256 * i;
            int r = idx >> 4;
            int j = jmin + r;
            if (j > 510) j = 510;   // window col 159 never consumed
            const float* src = (j < 256)
                ? (e1 + (size_t)(h * 256 + j) * D_DIM)
                : (e2 + (size_t)(h * 256 + j - 255) * D_DIM);
            v[i] = *reinterpret_cast<const float4*>(src + 4 * (idx & 15));
        }
        #pragma unroll
        for (int i = 0; i < 10; i++) {
            int idx = tid + 256 * i;
            int r = idx >> 4, m = idx & 15;
            uint32_t h0, l0, h1, l1;
            split2h(v[i].x, v[i].y, h0, l0);
            split2h(v[i].z, v[i].w, h1, l1);
            uint32_t* pH = reinterpret_cast<uint32_t*>(smem + SM_BH + r * RSTRIDE + 8 * m);
            uint32_t* pL = reinterpret_cast<uint32_t*>(smem + SM_BL + r * RSTRIDE + 8 * m);
            pH[0] = h0; pH[1] = h1;
            pL[0] = l0; pL[1] = l1;
        }
    }
    __syncthreads();

    // ---- warp tiling: 8 warps = 2 (M halves of 64) x 4 (N quarters of 40) ----
    const int wm = wid & 1;
    const int wn = wid >> 1;
    const int g  = lane >> 2;
    const int tg = lane & 3;

    float acc[4][5][4] = {};

    // A ldmatrix: rows wm*64 + (lane&15) + mt*16, k-chunk kk*2 + (lane>>4)
    const uint32_t aOff = (uint32_t)(wm * 64 + (lane & 15)) * RSTRIDE + (lane >> 4) * 16;
    // B x4 pair covers tiles (2p, 2p+1): rows wn*40 + p*16 + (lane>>4)*8 + (lane&7)
    const uint32_t bOff  = (uint32_t)(wn * 40 + (lane >> 4) * 8 + (lane & 7)) * RSTRIDE
                         + ((lane >> 3) & 1) * 16;
    const uint32_t bOff2 = (uint32_t)(wn * 40 + (lane & 7)) * RSTRIDE
                         + ((lane >> 3) & 1) * 16;    // x2 tail (tile 4)
    const uint32_t a0  = sb + SM_A  + aOff;
    const uint32_t bH0 = sb + SM_BH + bOff;
    const uint32_t bH2 = sb + SM_BH + bOff2;
    const uint32_t bL0 = sb + SM_BL + bOff;
    const uint32_t bL2 = sb + SM_BL + bOff2;

    #pragma unroll
    for (int kk = 0; kk < 4; kk++) {
        uint32_t a[4][4], bH[5][2], bL[5][2];
        // A fragments (shared by both passes)
        #pragma unroll
        for (int mt = 0; mt < 4; mt++)
            LDSM_X4(a[mt][0], a[mt][1], a[mt][2], a[mt][3],
                    a0 + mt * 16 * RSTRIDE + kk * 32);
        // pass 1: q̂ * Eh
        #pragma unroll
        for (int p = 0; p < 2; p++)
            LDSM_X4(bH[2*p][0], bH[2*p][1], bH[2*p+1][0], bH[2*p+1][1],
                    bH0 + p * 16 * RSTRIDE + kk * 32);
        LDSM_X2(bH[4][0], bH[4][1], bH2 + 32 * RSTRIDE + kk * 32);
        #pragma unroll
        for (int mt = 0; mt < 4; mt++)
            #pragma unroll
            for (int nt = 0; nt < 5; nt++)
                MMA16816(acc[mt][nt], a[mt], bH[nt]);
        // pass 2: q̂ * El
        #pragma unroll
        for (int p = 0; p < 2; p++)
            LDSM_X4(bL[2*p][0], bL[2*p][1], bL[2*p+1][0], bL[2*p+1][1],
                    bL0 + p * 16 * RSTRIDE + kk * 32);
        LDSM_X2(bL[4][0], bL[4][1], bL2 + 32 * RSTRIDE + kk * 32);
        #pragma unroll
        for (int mt = 0; mt < 4; mt++)
            #pragma unroll
            for (int nt = 0; nt < 5; nt++)
                MMA16816(acc[mt][nt], a[mt], bL[nt]);
    }
    __syncthreads();   // inputs dead; stage aliases them

    // ---- accum -> fp32 staging (window coords) ----
    float* st = reinterpret_cast<float*>(smem);
    #pragma unroll
    for (int mt = 0; mt < 4; mt++) {
        const int m0 = wm * 64 + mt * 16 + g;
        #pragma unroll
        for (int nt = 0; nt < 5; nt++) {
            const int n = wn * 40 + nt * 8 + 2 * tg;
            *reinterpret_cast<float2*>(&st[m0 * SP + n]) =
                make_float2(acc[mt][nt][0], acc[mt][nt][1]);
            *reinterpret_cast<float2*>(&st[(m0 + 8) * SP + n]) =
                make_float2(acc[mt][nt][2], acc[mt][nt][3]);
        }
    }
    __syncthreads();

    // ---- shifted read (column-strided, conflict-free) + coalesced writeout ----
    float* ob = out + ((size_t)b * T_DIM + t0) * S_DIM + 128 * sx;
    #pragma unroll
    for (int it = 0; it < 16; it++) {
        int idx = tid + 256 * it;
        int row = idx >> 5, m = idx & 31;
        int off = 31 - (row >> 2);
        const float* sr = &st[row * SP + off];
        float* orow = ob + row * S_DIM;
        #pragma unroll
        for (int k = 0; k < 4; k++)
            orow[m + 32 * k] = sr[m + 32 * k];
    }
}

extern "C" void kernel_launch(void* const* d_in, const int* in_sizes, int n_in,
                              void* d_out, int out_size)
{
    const float* q  = (const float*)d_in[0];
    const float* e1 = (const float*)d_in[1];
    const float* e2 = (const float*)d_in[2];
    float* out = (float*)d_out;

    cudaFuncSetAttribute(srel_mma,
                         cudaFuncAttributeMaxDynamicSharedMemorySize, SM_TOTAL);
    dim3 grid(T_DIM / BT, S_DIM / 128, 128);   // (8, 2, 128) = 2048 blocks
    srel_mma<<<grid, 256, SM_TOTAL>>>(q, e1, e2, out);
}

// round 12
// speedup vs baseline: 1.2718x; 1.1723x over previous
#include <cuda_runtime.h>
#include <cuda_fp16.h>
#include <cstdint>

// out[b,t,s] = dot(q[b,t,:], E_h[s - t/4 + 255]),  h = b % 8
//   E_h[j] = e1[h*256 + j]        j in [0,256)
//   E_h[j] = e2[h*256 + j - 255]  j in [256,511)
// B=128, T=1024, S=256, D=64.
//
// Per block: one b, 128 t-rows, 128 s-cols. Banded GEMM M=128 x N=160 x K=128:
//   fp16 2-pass: D = q̂·Eh + q̂·El,  q̂ = fp16(q), Eh = fp16(E), El = fp16(E-Eh)
// out[t][s] = D[t][ s + 31 - t/4 ]:
//   shift applied at stage-WRITE (predicated STS.32), readback LDS.128 + STG.128.

#define T_DIM 1024
#define S_DIM 256
#define D_DIM 64

constexpr int BT = 128;
constexpr int NW = 160;
constexpr int RSTRIDE = 144;     // bytes per fp16 row: conflict-free LDSM
constexpr int SP2 = 132;         // fp32 stage stride (floats), 128 cols used

constexpr int SM_A  = 0;
constexpr int SM_BH = SM_A  + BT * RSTRIDE;      // 18432
constexpr int SM_BL = SM_BH + NW * RSTRIDE;      // 41472
constexpr int SM_IN_END = SM_BL + NW * RSTRIDE;  // 64512
constexpr int SM_TOTAL = BT * SP2 * 4;           // 67584 (stage aliases inputs)
static_assert(SM_TOTAL >= SM_IN_END, "stage must cover inputs");

__device__ __forceinline__ uint32_t smem_u32(const void* p) {
    uint32_t a;
    asm("{ .reg .u64 t; cvta.to.shared.u64 t, %1; cvt.u32.u64 %0, t; }"
        : "=r"(a) : "l"(p));
    return a;
}

#define LDSM_X4(r0, r1, r2, r3, addr)                                        \
    asm volatile("ldmatrix.sync.aligned.m8n8.x4.shared.b16 {%0,%1,%2,%3}, [%4];" \
                 : "=r"(r0), "=r"(r1), "=r"(r2), "=r"(r3) : "r"(addr))

#define LDSM_X2(r0, r1, addr)                                                \
    asm volatile("ldmatrix.sync.aligned.m8n8.x2.shared.b16 {%0,%1}, [%2];"   \
                 : "=r"(r0), "=r"(r1) : "r"(addr))

#define MMA16816(d, a, bb)                                                   \
    asm volatile("mma.sync.aligned.m16n8k16.row.col.f32.f16.f16.f32 "        \
                 "{%0,%1,%2,%3}, {%4,%5,%6,%7}, {%8,%9}, {%0,%1,%2,%3};"     \
                 : "+f"((d)[0]), "+f"((d)[1]), "+f"((d)[2]), "+f"((d)[3])    \
                 : "r"((a)[0]), "r"((a)[1]), "r"((a)[2]), "r"((a)[3]),       \
                   "r"((bb)[0]), "r"((bb)[1]))

// fp16 split of two floats: hi = rn(fp16), lo = rn(fp16(residual))
__device__ __forceinline__ void split2h(float a, float b, uint32_t& hi, uint32_t& lo) {
    __half2 H = __floats2half2_rn(a, b);
    float ra = a - __half2float(__low2half(H));
    float rb = b - __half2float(__high2half(H));
    __half2 L = __floats2half2_rn(ra, rb);
    hi = *reinterpret_cast<uint32_t*>(&H);
    lo = *reinterpret_cast<uint32_t*>(&L);
}

__global__ void __launch_bounds__(256, 2)
srel_mma(const float* __restrict__ q,
         const float* __restrict__ e1,
         const float* __restrict__ e2,
         float* __restrict__ out)
{
    extern __shared__ char smem[];
    const uint32_t sb = smem_u32(smem);
    const int tid  = threadIdx.x;
    const int lane = tid & 31;
    const int wid  = tid >> 5;

    const int b   = blockIdx.z;
    const int h   = b & 7;
    const int t0  = blockIdx.x * BT;
    const int sx  = blockIdx.y;
    const int sh0 = t0 >> 2;
    const int jmin = 128 * sx + 224 - sh0;   // window col c = j - jmin, c in [0,159]

    // ---- stage Q as single fp16 tile (batch LDG for MLP) ----
    {
        const float* qb = q + ((size_t)b * T_DIM + t0) * D_DIM;
        float4 v[8];
        #pragma unroll
        for (int i = 0; i < 8; i++) {
            int idx = tid + 256 * i;
            v[i] = *reinterpret_cast<const float4*>(qb + (idx >> 4) * D_DIM + 4 * (idx & 15));
        }
        #pragma unroll
        for (int i = 0; i < 8; i++) {
            int idx = tid + 256 * i;
            int row = idx >> 4, m = idx & 15;
            __half2 h0 = __floats2half2_rn(v[i].x, v[i].y);
            __half2 h1 = __floats2half2_rn(v[i].z, v[i].w);
            uint32_t* pA = reinterpret_cast<uint32_t*>(smem + SM_A + row * RSTRIDE + 8 * m);
            pA[0] = *reinterpret_cast<uint32_t*>(&h0);
            pA[1] = *reinterpret_cast<uint32_t*>(&h1);
        }
    }
    // ---- stage E window: fp16 hi/lo tiles ----
    {
        float4 v[10];
        #pragma unroll
        for (int i = 0; i < 10; i++) {
            int idx = tid + 256 * i;
            int r = idx >> 4;
            int j = jmin + r;
            if (j > 510) j = 510;   // window col 159 never consumed
            const float* src = (j < 256)
                ? (e1 + (size_t)(h * 256 + j) * D_DIM)
                : (e2 + (size_t)(h * 256 + j - 255) * D_DIM);
            v[i] = *reinterpret_cast<const float4*>(src + 4 * (idx & 15));
        }
        #pragma unroll
        for (int i = 0; i < 10; i++) {
            int idx = tid + 256 * i;
            int r = idx >> 4, m = idx & 15;
            uint32_t h0, l0, h1, l1;
            split2h(v[i].x, v[i].y, h0, l0);
            split2h(v[i].z, v[i].w, h1, l1);
            uint32_t* pH = reinterpret_cast<uint32_t*>(smem + SM_BH + r * RSTRIDE + 8 * m);
            uint32_t* pL = reinterpret_cast<uint32_t*>(smem + SM_BL + r * RSTRIDE + 8 * m);
            pH[0] = h0; pH[1] = h1;
            pL[0] = l0; pL[1] = l1;
        }
    }
    __syncthreads();

    // ---- warp tiling: 8 warps = 2 (M halves of 64) x 4 (N quarters of 40) ----
    const int wm = wid & 1;
    const int wn = wid >> 1;
    const int g  = lane >> 2;
    const int tg = lane & 3;

    float acc[4][5][4] = {};

    const uint32_t aOff = (uint32_t)(wm * 64 + (lane & 15)) * RSTRIDE + (lane >> 4) * 16;
    const uint32_t bOff  = (uint32_t)(wn * 40 + (lane >> 4) * 8 + (lane & 7)) * RSTRIDE
                         + ((lane >> 3) & 1) * 16;
    const uint32_t bOff2 = (uint32_t)(wn * 40 + (lane & 7)) * RSTRIDE
                         + ((lane >> 3) & 1) * 16;    // x2 tail (tile 4)
    const uint32_t a0  = sb + SM_A  + aOff;
    const uint32_t bH0 = sb + SM_BH + bOff;
    const uint32_t bH2 = sb + SM_BH + bOff2;
    const uint32_t bL0 = sb + SM_BL + bOff;
    const uint32_t bL2 = sb + SM_BL + bOff2;

    #pragma unroll
    for (int kk = 0; kk < 4; kk++) {
        uint32_t a[4][4], bH[5][2], bL[5][2];
        #pragma unroll
        for (int mt = 0; mt < 4; mt++)
            LDSM_X4(a[mt][0], a[mt][1], a[mt][2], a[mt][3],
                    a0 + mt * 16 * RSTRIDE + kk * 32);
        // pass 1: q̂ * Eh
        #pragma unroll
        for (int p = 0; p < 2; p++)
            LDSM_X4(bH[2*p][0], bH[2*p][1], bH[2*p+1][0], bH[2*p+1][1],
                    bH0 + p * 16 * RSTRIDE + kk * 32);
        LDSM_X2(bH[4][0], bH[4][1], bH2 + 32 * RSTRIDE + kk * 32);
        #pragma unroll
        for (int mt = 0; mt < 4; mt++)
            #pragma unroll
            for (int nt = 0; nt < 5; nt++)
                MMA16816(acc[mt][nt], a[mt], bH[nt]);
        // pass 2: q̂ * El
        #pragma unroll
        for (int p = 0; p < 2; p++)
            LDSM_X4(bL[2*p][0], bL[2*p][1], bL[2*p+1][0], bL[2*p+1][1],
                    bL0 + p * 16 * RSTRIDE + kk * 32);
        LDSM_X2(bL[4][0], bL[4][1], bL2 + 32 * RSTRIDE + kk * 32);
        #pragma unroll
        for (int mt = 0; mt < 4; mt++)
            #pragma unroll
            for (int nt = 0; nt < 5; nt++)
                MMA16816(acc[mt][nt], a[mt], bL[nt]);
    }
    __syncthreads();   // inputs dead; stage aliases them

    // ---- accum -> stage with PRE-SHIFTED predicated STS.32 ----
    // row r: stage col = n - off(r), off = 31 - r/4; coverage of [0,128) exact.
    float* st = reinterpret_cast<float*>(smem);
    #pragma unroll
    for (int mt = 0; mt < 4; mt++) {
        const int r0 = wm * 64 + mt * 16 + g;        // rows r0, r0+8
        const int off0 = 31 - (r0 >> 2);
        const int off1 = off0 - 2;
        float* s0 = &st[r0 * SP2];
        float* s1 = &st[(r0 + 8) * SP2];
        #pragma unroll
        for (int nt = 0; nt < 5; nt++) {
            const int n = wn * 40 + nt * 8 + 2 * tg;
            int c0 = n - off0;
            int c1 = n - off1;
            if ((unsigned)c0       < 128u) s0[c0]     = acc[mt][nt][0];
            if ((unsigned)(c0 + 1) < 128u) s0[c0 + 1] = acc[mt][nt][1];
            if ((unsigned)c1       < 128u) s1[c1]     = acc[mt][nt][2];
            if ((unsigned)(c1 + 1) < 128u) s1[c1 + 1] = acc[mt][nt][3];
        }
    }
    __syncthreads();

    // ---- aligned LDS.128 readback + coalesced STG.128 writeout ----
    float* ob = out + ((size_t)b * T_DIM + t0) * S_DIM + 128 * sx;
    #pragma unroll
    for (int it = 0; it < 4; it++) {
        float4 v[4];
        #pragma unroll
        for (int j = 0; j < 4; j++) {
            int idx = tid + 256 * (4 * it + j);
            int row = idx >> 5, m = idx & 31;   // one row per warp
            v[j] = *reinterpret_cast<const float4*>(&st[row * SP2 + 4 * m]);
        }
        #pragma unroll
        for (int j = 0; j < 4; j++) {
            int idx = tid + 256 * (4 * it + j);
            int row = idx >> 5, m = idx & 31;
            *reinterpret_cast<float4*>(ob + row * S_DIM + 4 * m) = v[j];
        }
    }
}

extern "C" void kernel_launch(void* const* d_in, const int* in_sizes, int n_in,
                              void* d_out, int out_size)
{
    const float* q  = (const float*)d_in[0];
    const float* e1 = (const float*)d_in[1];
    const float* e2 = (const float*)d_in[2];
    float* out = (float*)d_out;

    cudaFuncSetAttribute(srel_mma,
                         cudaFuncAttributeMaxDynamicSharedMemorySize, SM_TOTAL);
    dim3 grid(T_DIM / BT, S_DIM / 128, 128);   // (8, 2, 128) = 2048 blocks
    srel_mma<<<grid, 256, SM_TOTAL>>>(q, e1, e2, out);
}

// round 13
// speedup vs baseline: 1.3174x; 1.0358x over previous
#include <cuda_runtime.h>
#include <cuda_fp16.h>
#include <cstdint>

// out[b,t,s] = dot(q[b,t,:], E_h[s - t/4 + 255]),  h = b % 8
//   E_h[j] = e1[h*256 + j]        j in [0,256)
//   E_h[j] = e2[h*256 + j - 255]  j in [256,511)
// B=128, T=1024, S=256, D=64.
//
// Per block: one b, 128 t-rows, 128 s-cols. Banded GEMM M=128 x N=160 x K=128:
//   fp16 2-pass: D = q̂·Eh + q̂·El,  q̂ = fp16(q), Eh = fp16(E), El = fp16(E-Eh)
// out[t][s] = D[t][ s + 31 - t/4 ]:
//   pre-shifted predicated STS.32 stage write, wm-split named-barrier,
//   LDS.128 + STG.128 readback.

#define T_DIM 1024
#define S_DIM 256
#define D_DIM 64

constexpr int BT = 128;
constexpr int NW = 160;
constexpr int RSTRIDE = 144;     // bytes per fp16 row: conflict-free LDSM
constexpr int SP2 = 132;         // fp32 stage stride (floats), 128 cols used

constexpr int SM_A  = 0;
constexpr int SM_BH = SM_A  + BT * RSTRIDE;      // 18432
constexpr int SM_BL = SM_BH + NW * RSTRIDE;      // 41472
constexpr int SM_IN_END = SM_BL + NW * RSTRIDE;  // 64512
constexpr int SM_TOTAL = BT * SP2 * 4;           // 67584 (stage aliases inputs)
static_assert(SM_TOTAL >= SM_IN_END, "stage must cover inputs");

__device__ __forceinline__ uint32_t smem_u32(const void* p) {
    uint32_t a;
    asm("{ .reg .u64 t; cvta.to.shared.u64 t, %1; cvt.u32.u64 %0, t; }"
        : "=r"(a) : "l"(p));
    return a;
}

#define LDSM_X4(r0, r1, r2, r3, addr)                                        \
    asm volatile("ldmatrix.sync.aligned.m8n8.x4.shared.b16 {%0,%1,%2,%3}, [%4];" \
                 : "=r"(r0), "=r"(r1), "=r"(r2), "=r"(r3) : "r"(addr))

#define LDSM_X2(r0, r1, addr)                                                \
    asm volatile("ldmatrix.sync.aligned.m8n8.x2.shared.b16 {%0,%1}, [%2];"   \
                 : "=r"(r0), "=r"(r1) : "r"(addr))

#define MMA16816(d, a, bb)                                                   \
    asm volatile("mma.sync.aligned.m16n8k16.row.col.f32.f16.f16.f32 "        \
                 "{%0,%1,%2,%3}, {%4,%5,%6,%7}, {%8,%9}, {%0,%1,%2,%3};"     \
                 : "+f"((d)[0]), "+f"((d)[1]), "+f"((d)[2]), "+f"((d)[3])    \
                 : "r"((a)[0]), "r"((a)[1]), "r"((a)[2]), "r"((a)[3]),       \
                   "r"((bb)[0]), "r"((bb)[1]))

__device__ __forceinline__ uint32_t h2bits(__half2 v) {
    return *reinterpret_cast<uint32_t*>(&v);
}

// fp16 split of 8 floats (two float4): hi = rn(fp16), lo = rn(fp16(residual))
__device__ __forceinline__ void split4h(float4 a, float4 b, uint4& hi, uint4& lo) {
    __half2 H0 = __floats2half2_rn(a.x, a.y);
    __half2 H1 = __floats2half2_rn(a.z, a.w);
    __half2 H2 = __floats2half2_rn(b.x, b.y);
    __half2 H3 = __floats2half2_rn(b.z, b.w);
    __half2 L0 = __floats2half2_rn(a.x - __low2float(H0), a.y - __high2float(H0));
    __half2 L1 = __floats2half2_rn(a.z - __low2float(H1), a.w - __high2float(H1));
    __half2 L2 = __floats2half2_rn(b.x - __low2float(H2), b.y - __high2float(H2));
    __half2 L3 = __floats2half2_rn(b.z - __low2float(H3), b.w - __high2float(H3));
    hi.x = h2bits(H0); hi.y = h2bits(H1); hi.z = h2bits(H2); hi.w = h2bits(H3);
    lo.x = h2bits(L0); lo.y = h2bits(L1); lo.z = h2bits(L2); lo.w = h2bits(L3);
}

__global__ void __launch_bounds__(256, 2)
srel_mma(const float* __restrict__ q,
         const float* __restrict__ e1,
         const float* __restrict__ e2,
         float* __restrict__ out)
{
    extern __shared__ char smem[];
    const uint32_t sb = smem_u32(smem);
    const int tid  = threadIdx.x;
    const int lane = tid & 31;
    const int wid  = tid >> 5;

    const int b   = blockIdx.z;
    const int h   = b & 7;
    const int t0  = blockIdx.x * BT;
    const int sx  = blockIdx.y;
    const int sh0 = t0 >> 2;
    const int jmin = 128 * sx + 224 - sh0;   // window col c = j - jmin, c in [0,159]

    // ---- stage Q: fp16 tile via float4-pairs -> STS.128 ----
    {
        const float* qb = q + ((size_t)b * T_DIM + t0) * D_DIM;
        float4 va[4], vb[4];
        #pragma unroll
        for (int i = 0; i < 4; i++) {
            int idx = tid + 256 * i;                    // pair index: r = idx>>3, mp = idx&7
            const float* p = qb + (idx >> 3) * D_DIM + 8 * (idx & 7);
            va[i] = *reinterpret_cast<const float4*>(p);
            vb[i] = *reinterpret_cast<const float4*>(p + 4);
        }
        #pragma unroll
        for (int i = 0; i < 4; i++) {
            int idx = tid + 256 * i;
            int r = idx >> 3, mp = idx & 7;
            uint4 u;
            u.x = h2bits(__floats2half2_rn(va[i].x, va[i].y));
            u.y = h2bits(__floats2half2_rn(va[i].z, va[i].w));
            u.z = h2bits(__floats2half2_rn(vb[i].x, vb[i].y));
            u.w = h2bits(__floats2half2_rn(vb[i].z, vb[i].w));
            *reinterpret_cast<uint4*>(smem + SM_A + r * RSTRIDE + 16 * mp) = u;
        }
    }
    // ---- stage E window: fp16 hi/lo tiles via float4-pairs -> STS.128 ----
    {
        float4 va[5], vb[5];
        #pragma unroll
        for (int i = 0; i < 5; i++) {
            int idx = tid + 256 * i;                    // 160 rows x 8 pairs
            int r = idx >> 3;
            int j = jmin + r;
            if (j > 510) j = 510;   // window col 159 never consumed
            const float* src = (j < 256)
                ? (e1 + (size_t)(h * 256 + j) * D_DIM)
                : (e2 + (size_t)(h * 256 + j - 255) * D_DIM);
            const float* p = src + 8 * (idx & 7);
            va[i] = *reinterpret_cast<const float4*>(p);
            vb[i] = *reinterpret_cast<const float4*>(p + 4);
        }
        #pragma unroll
        for (int i = 0; i < 5; i++) {
            int idx = tid + 256 * i;
            int r = idx >> 3, mp = idx & 7;
            uint4 hi, lo;
            split4h(va[i], vb[i], hi, lo);
            *reinterpret_cast<uint4*>(smem + SM_BH + r * RSTRIDE + 16 * mp) = hi;
            *reinterpret_cast<uint4*>(smem + SM_BL + r * RSTRIDE + 16 * mp) = lo;
        }
    }
    __syncthreads();

    // ---- warp tiling: 8 warps = 2 (M halves of 64) x 4 (N quarters of 40) ----
    const int wm = wid & 1;
    const int wn = wid >> 1;
    const int g  = lane >> 2;
    const int tg = lane & 3;

    float acc[4][5][4] = {};

    const uint32_t aOff = (uint32_t)(wm * 64 + (lane & 15)) * RSTRIDE + (lane >> 4) * 16;
    const uint32_t bOff  = (uint32_t)(wn * 40 + (lane >> 4) * 8 + (lane & 7)) * RSTRIDE
                         + ((lane >> 3) & 1) * 16;
    const uint32_t bOff2 = (uint32_t)(wn * 40 + (lane & 7)) * RSTRIDE
                         + ((lane >> 3) & 1) * 16;    // x2 tail (tile 4)
    const uint32_t a0  = sb + SM_A  + aOff;
    const uint32_t bH0 = sb + SM_BH + bOff;
    const uint32_t bH2 = sb + SM_BH + bOff2;
    const uint32_t bL0 = sb + SM_BL + bOff;
    const uint32_t bL2 = sb + SM_BL + bOff2;

    #pragma unroll
    for (int kk = 0; kk < 4; kk++) {
        uint32_t a[4][4], bH[5][2], bL[5][2];
        // issue ALL fragment loads up front (bL hoisted: pass-2 never stalls on LDSM)
        #pragma unroll
        for (int mt = 0; mt < 4; mt++)
            LDSM_X4(a[mt][0], a[mt][1], a[mt][2], a[mt][3],
                    a0 + mt * 16 * RSTRIDE + kk * 32);
        #pragma unroll
        for (int p = 0; p < 2; p++)
            LDSM_X4(bH[2*p][0], bH[2*p][1], bH[2*p+1][0], bH[2*p+1][1],
                    bH0 + p * 16 * RSTRIDE + kk * 32);
        LDSM_X2(bH[4][0], bH[4][1], bH2 + 32 * RSTRIDE + kk * 32);
        #pragma unroll
        for (int p = 0; p < 2; p++)
            LDSM_X4(bL[2*p][0], bL[2*p][1], bL[2*p+1][0], bL[2*p+1][1],
                    bL0 + p * 16 * RSTRIDE + kk * 32);
        LDSM_X2(bL[4][0], bL[4][1], bL2 + 32 * RSTRIDE + kk * 32);
        // pass 1: q̂ * Eh
        #pragma unroll
        for (int mt = 0; mt < 4; mt++)
            #pragma unroll
            for (int nt = 0; nt < 5; nt++)
                MMA16816(acc[mt][nt], a[mt], bH[nt]);
        // pass 2: q̂ * El
        #pragma unroll
        for (int mt = 0; mt < 4; mt++)
            #pragma unroll
            for (int nt = 0; nt < 5; nt++)
                MMA16816(acc[mt][nt], a[mt], bL[nt]);
    }
    __syncthreads();   // inputs dead; stage aliases them

    // ---- accum -> stage with PRE-SHIFTED predicated STS.32 ----
    // row r: stage col = n - off(r), off = 31 - r/4; coverage of [0,128) exact.
    float* st = reinterpret_cast<float*>(smem);
    #pragma unroll
    for (int mt = 0; mt < 4; mt++) {
        const int r0 = wm * 64 + mt * 16 + g;        // rows r0, r0+8
        const int off0 = 31 - (r0 >> 2);
        const int off1 = off0 - 2;
        float* s0 = &st[r0 * SP2];
        float* s1 = &st[(r0 + 8) * SP2];
        #pragma unroll
        for (int nt = 0; nt < 5; nt++) {
            const int n = wn * 40 + nt * 8 + 2 * tg;
            int c0 = n - off0;
            int c1 = n - off1;
            if ((unsigned)c0       < 128u) s0[c0]     = acc[mt][nt][0];
            if ((unsigned)(c0 + 1) < 128u) s0[c0 + 1] = acc[mt][nt][1];
            if ((unsigned)c1       < 128u) s1[c1]     = acc[mt][nt][2];
            if ((unsigned)(c1 + 1) < 128u) s1[c1 + 1] = acc[mt][nt][3];
        }
    }
    // wm-half barrier: rows [wm*64, wm*64+64) are written only by wm-group warps
    asm volatile("bar.sync %0, 128;" :: "r"(1 + wm) : "memory");

    // ---- aligned LDS.128 readback + coalesced STG.128, wm-local rows ----
    float* ob = out + ((size_t)b * T_DIM + t0) * S_DIM + 128 * sx;
    const int lw = wid >> 1;     // warp index within wm-group (0..3)
    #pragma unroll
    for (int i = 0; i < 16; i++) {
        int row = wm * 64 + i * 4 + lw;
        float4 v = *reinterpret_cast<const float4*>(&st[row * SP2 + 4 * lane]);
        *reinterpret_cast<float4*>(ob + row * S_DIM + 4 * lane) = v;
    }
}

extern "C" void kernel_launch(void* const* d_in, const int* in_sizes, int n_in,
                              void* d_out, int out_size)
{
    const float* q  = (const float*)d_in[0];
    const float* e1 = (const float*)d_in[1];
    const float* e2 = (const float*)d_in[2];
    float* out = (float*)d_out;

    cudaFuncSetAttribute(srel_mma,
                         cudaFuncAttributeMaxDynamicSharedMemorySize, SM_TOTAL);
    dim3 grid(T_DIM / BT, S_DIM / 128, 128);   // (8, 2, 128) = 2048 blocks
    srel_mma<<<grid, 256, SM_TOTAL>>>(q, e1, e2, out);
}